// round 16
// baseline (speedup 1.0000x reference)
#include <cuda_runtime.h>
#include <cuda_bf16.h>
#include <cuda_fp16.h>
#include <math.h>
#include <stdint.h>

// Problem constants
#define BB   64
#define TT   256
#define DD   1024
#define HH   16
#define DH   64
#define BT   (BB*TT)      // 16384
#define HB   (HH*BB)      // 1024
#define TS   (TT*TT)      // 65536

#define UNIF (1.0f / 1024.0f)   // exactly representable in bf16

// ---------------------------------------------------------------------------
// Scratch (__device__ globals; no allocation allowed)
// ---------------------------------------------------------------------------
__device__ __half g_ah[BT * DD];                // 32 MB (fp16 hi of x+pos)
__device__ __half g_al[BT * DD];                // 32 MB (fp16 lo)
__device__ __half g_wt[3][DD * DD];             // 2 MB x3 (fp16, transposed [n][k])
__device__ __nv_bfloat16 g_qhi[BT * DD];        // 32 MB
__device__ __nv_bfloat16 g_qlo[BT * DD];        // 32 MB
__device__ __nv_bfloat16 g_khi[BT * DD];        // 32 MB
__device__ __nv_bfloat16 g_klo[BT * DD];        // 32 MB
__device__ float g_v[BT * DD];                  // 64 MB
__device__ __half g_scores[(size_t)HB * TS];    // 128 MB (fp16 raw scores, s>t valid)
__device__ float g_inv[TS];                     // 256 KB

// ---------------------------------------------------------------------------
// helpers
// ---------------------------------------------------------------------------
__device__ __forceinline__ uint32_t smem_u32(const void* p) {
    uint32_t a;
    asm("{ .reg .u64 t; cvta.to.shared.u64 t, %1; cvt.u32.u64 %0, t; }" : "=r"(a) : "l"(p));
    return a;
}
__device__ __forceinline__ void ldsm4(uint32_t* r, uint32_t a) {
    asm volatile("ldmatrix.sync.aligned.m8n8.x4.shared.b16 {%0,%1,%2,%3}, [%4];"
                 : "=r"(r[0]), "=r"(r[1]), "=r"(r[2]), "=r"(r[3]) : "r"(a));
}
__device__ __forceinline__ void ldsm4t(uint32_t* r, uint32_t a) {
    asm volatile("ldmatrix.sync.aligned.m8n8.x4.trans.shared.b16 {%0,%1,%2,%3}, [%4];"
                 : "=r"(r[0]), "=r"(r[1]), "=r"(r[2]), "=r"(r[3]) : "r"(a));
}
__device__ __forceinline__ void mma16816(float* c, const uint32_t* a, const uint32_t* b) {
    asm volatile(
        "mma.sync.aligned.m16n8k16.row.col.f32.bf16.bf16.f32 "
        "{%0,%1,%2,%3}, {%4,%5,%6,%7}, {%8,%9}, {%0,%1,%2,%3};"
        : "+f"(c[0]), "+f"(c[1]), "+f"(c[2]), "+f"(c[3])
        : "r"(a[0]), "r"(a[1]), "r"(a[2]), "r"(a[3]), "r"(b[0]), "r"(b[1]));
}
__device__ __forceinline__ void mma16816h(float* c, const uint32_t* a, const uint32_t* b) {
    asm volatile(
        "mma.sync.aligned.m16n8k16.row.col.f32.f16.f16.f32 "
        "{%0,%1,%2,%3}, {%4,%5,%6,%7}, {%8,%9}, {%0,%1,%2,%3};"
        : "+f"(c[0]), "+f"(c[1]), "+f"(c[2]), "+f"(c[3])
        : "r"(a[0]), "r"(a[1]), "r"(a[2]), "r"(a[3]), "r"(b[0]), "r"(b[1]));
}
#define CP16(sa, gp) \
    asm volatile("cp.async.cg.shared.global [%0], [%1], 16;" :: "r"(sa), "l"(gp))
#define CP_COMMIT() asm volatile("cp.async.commit_group;" ::: "memory")
#define CP_WAIT(n)  asm volatile("cp.async.wait_group %0;" :: "n"(n) : "memory")

__device__ __forceinline__ void split_bf16(float a, __nv_bfloat16& h, __nv_bfloat16& l) {
    h = __float2bfloat16_rn(a);
    l = __float2bfloat16_rn(a - __bfloat162float(h));
}
__device__ __forceinline__ void split_fp16(float a, __half& h, __half& l) {
    h = __float2half_rn(a);
    l = __float2half_rn(a - __half2float(h));
}

// ---------------------------------------------------------------------------
// Kernel 1: (x + pos) -> split into fp16 hi/lo
// ---------------------------------------------------------------------------
__global__ void add_split_kernel(const float* __restrict__ x,
                                 const float* __restrict__ pos,
                                 __half* __restrict__ ah,
                                 __half* __restrict__ al) {
    int i4 = blockIdx.x * blockDim.x + threadIdx.x;
    int n4 = BT * DD / 4;
    if (i4 >= n4) return;
    int td4 = i4 % (TT * DD / 4);
    float4 xv = ((const float4*)x)[i4];
    float4 pv = ((const float4*)pos)[td4];
    float a[4] = {xv.x + pv.x, xv.y + pv.y, xv.z + pv.z, xv.w + pv.w};
    __half hi[4], lo[4];
#pragma unroll
    for (int j = 0; j < 4; j++) split_fp16(a[j], hi[j], lo[j]);
    __half2 h0; h0.x = hi[0]; h0.y = hi[1];
    __half2 h1; h1.x = hi[2]; h1.y = hi[3];
    __half2 l0; l0.x = lo[0]; l0.y = lo[1];
    __half2 l1; l1.x = lo[2]; l1.y = lo[3];
    ((__half2*)ah)[i4 * 2 + 0] = h0;
    ((__half2*)ah)[i4 * 2 + 1] = h1;
    ((__half2*)al)[i4 * 2 + 0] = l0;
    ((__half2*)al)[i4 * 2 + 1] = l1;
}

// ---------------------------------------------------------------------------
// Kernel 2: weight transpose + fp16 convert:  Wt[n][k] = fp16(W[k][n])
// ---------------------------------------------------------------------------
__global__ void wsplit_kernel(const float* __restrict__ W,
                              __half* __restrict__ wt) {
    __shared__ float tile[32][33];
    int k0 = blockIdx.x * 32;
    int n0 = blockIdx.y * 32;
    int tx = threadIdx.x;
    int ty = threadIdx.y;
#pragma unroll
    for (int i = 0; i < 32; i += 8)
        tile[ty + i][tx] = W[(size_t)(k0 + ty + i) * DD + n0 + tx];
    __syncthreads();
#pragma unroll
    for (int i = 0; i < 32; i += 8) {
        float v = tile[tx][ty + i];
        wt[(size_t)(n0 + ty + i) * DD + k0 + tx] = __float2half_rn(v);
    }
}

// ---------------------------------------------------------------------------
// Kernel 3: merged HMMA projection GEMM (fp16 2-product: aH*W + aL*W).
// ---------------------------------------------------------------------------
#define G_BM 128
#define G_BN 256
#define G_BK 32
#define G_NCH (DD / G_BK)        // 32
#define G_RS 40                   // smem row stride in halfs (80 B)
#define OFF_AH 0
#define OFF_AL (G_BM * G_RS * 2)                  // 10240
#define OFF_BH (2 * G_BM * G_RS * 2)              // 20480
#define G_STAGE (OFF_BH + G_BN * G_RS * 2)        // 40960
#define G_NSTAGE 3
#define GEMM_SMEM (G_NSTAGE * G_STAGE)            // 122880

__global__ __launch_bounds__(512) void gemm_hmma_kernel(
    const __half* __restrict__ Ah, const __half* __restrict__ Al,
    const __half* __restrict__ Wt,
    __nv_bfloat16* __restrict__ Qhi, __nv_bfloat16* __restrict__ Qlo,
    __nv_bfloat16* __restrict__ Khi, __nv_bfloat16* __restrict__ Klo,
    float* __restrict__ V)
{
    extern __shared__ char smem[];
    const uint32_t sb = smem_u32(smem);
    const int tid = threadIdx.x;
    const int lane = tid & 31;
    const int wid = tid >> 5;
    const int wm = wid & 3;
    const int wn = wid >> 2;
    const int z = blockIdx.x >> 2;
    const int brow = blockIdx.y * G_BM;
    const int bcol = (blockIdx.x & 3) * G_BN;

    const __half* Bh = Wt + (size_t)z * DD * DD;

    const int acrow = tid >> 2;
    const int acseg = tid & 3;
    const uint32_t a_soff = (uint32_t)(acrow * (G_RS * 2) + acseg * 16);
    const size_t ga_base = (size_t)(brow + acrow) * DD + acseg * 8;

    float acc[2][8][4];
#pragma unroll
    for (int mt = 0; mt < 2; mt++)
#pragma unroll
        for (int nt = 0; nt < 8; nt++)
#pragma unroll
            for (int i = 0; i < 4; i++) acc[mt][nt][i] = 0.0f;

    auto load_stage = [&](int ch, int stg) {
        uint32_t st = sb + stg * G_STAGE;
        size_t goff = (size_t)ch * G_BK;
        CP16(st + OFF_AH + a_soff, Ah + ga_base + goff);
        CP16(st + OFF_AL + a_soff, Al + ga_base + goff);
#pragma unroll
        for (int i = 0; i < 2; i++) {
            int idx = tid + i * 512;
            int r = idx >> 2;
            int seg = idx & 3;
            uint32_t so = (uint32_t)(r * (G_RS * 2) + seg * 16);
            size_t gb = (size_t)(bcol + r) * DD + seg * 8 + goff;
            CP16(st + OFF_BH + so, Bh + gb);
        }
        CP_COMMIT();
    };

    load_stage(0, 0);
    load_stage(1, 1);

    const int a_row = lane & 15;
    const int a_k8  = (lane >> 4) * 8;
    const int b_row = (lane & 7) + ((lane & 16) ? 8 : 0);
    const int b_k8  = (lane & 8) ? 8 : 0;

    for (int ch = 0; ch < G_NCH; ch++) {
        if (ch + 2 < G_NCH) {
            load_stage(ch + 2, (ch + 2) % G_NSTAGE);
            CP_WAIT(2);
        } else if (ch + 1 < G_NCH) {
            CP_WAIT(1);
        } else {
            CP_WAIT(0);
        }
        __syncthreads();

        const uint32_t st = sb + (ch % G_NSTAGE) * G_STAGE;
#pragma unroll
        for (int ks = 0; ks < 2; ks++) {
            uint32_t aH[2][4], aL[2][4];
#pragma unroll
            for (int mt = 0; mt < 2; mt++) {
                uint32_t ao = st + OFF_AH +
                    (uint32_t)((wm * 32 + mt * 16 + a_row) * (G_RS * 2) +
                               (ks * 16 + a_k8) * 2);
                ldsm4(aH[mt], ao);
                ldsm4(aL[mt], ao + (OFF_AL - OFF_AH));
            }
#pragma unroll
            for (int ph = 0; ph < 2; ph++) {
                uint32_t bH[2][4];
#pragma unroll
                for (int p = 0; p < 2; p++) {
                    uint32_t bo = st + OFF_BH +
                        (uint32_t)((wn * 64 + (ph * 2 + p) * 16 + b_row) * (G_RS * 2) +
                                   (ks * 16 + b_k8) * 2);
                    ldsm4(bH[p], bo);
                }
#pragma unroll
                for (int mt = 0; mt < 2; mt++)
#pragma unroll
                    for (int nl = 0; nl < 4; nl++) {
                        const uint32_t* bhp = &bH[nl >> 1][(nl & 1) * 2];
                        float* a = acc[mt][ph * 4 + nl];
                        mma16816h(a, aH[mt], bhp);
                        mma16816h(a, aL[mt], bhp);
                    }
            }
        }
        __syncthreads();
    }

    __nv_bfloat16* Ohi = (z == 0) ? Qhi : Khi;
    __nv_bfloat16* Olo = (z == 0) ? Qlo : Klo;
#pragma unroll
    for (int mt = 0; mt < 2; mt++) {
        int row = brow + wm * 32 + mt * 16 + (lane >> 2);
#pragma unroll
        for (int nt = 0; nt < 8; nt++) {
            int col = bcol + wn * 64 + nt * 8 + (lane & 3) * 2;
            if (z == 2) {
                *(float2*)(V + (size_t)row * DD + col) =
                    make_float2(acc[mt][nt][0], acc[mt][nt][1]);
                *(float2*)(V + (size_t)(row + 8) * DD + col) =
                    make_float2(acc[mt][nt][2], acc[mt][nt][3]);
            } else {
#pragma unroll
                for (int half = 0; half < 2; half++) {
                    int r = row + half * 8;
                    __nv_bfloat16 h0, l0, h1, l1;
                    split_bf16(acc[mt][nt][half * 2 + 0], h0, l0);
                    split_bf16(acc[mt][nt][half * 2 + 1], h1, l1);
                    __nv_bfloat162 hp; hp.x = h0; hp.y = h1;
                    __nv_bfloat162 lp; lp.x = l0; lp.y = l1;
                    *(__nv_bfloat162*)(Ohi + (size_t)r * DD + col) = hp;
                    *(__nv_bfloat162*)(Olo + (size_t)r * DD + col) = lp;
                }
            }
        }
    }
}

// ---------------------------------------------------------------------------
// Kernel 4: HMMA scores, 64x64 upper tiles (bf16 3-product, proven).
// Stores scores as fp16 (half the write traffic).
// ---------------------------------------------------------------------------
#define SC_STR 72   // smem row stride in halfs (144B)

__global__ __launch_bounds__(256) void scores_hmma_kernel(
    const __nv_bfloat16* __restrict__ qhi, const __nv_bfloat16* __restrict__ qlo,
    const __nv_bfloat16* __restrict__ khi, const __nv_bfloat16* __restrict__ klo,
    __half* __restrict__ scores)
{
    const int t0 = blockIdx.y * 64;
    const int s0 = blockIdx.x * 64;
    if (s0 < t0) return;   // fully masked tile
    const int bh = blockIdx.z;
    const int b = bh & (BB - 1);
    const int h = bh >> 6;

    __shared__ __nv_bfloat16 sm[4][64 * SC_STR];

    const int tid = threadIdx.x;
    const int lane = tid & 31;
    const int wid = tid >> 5;
    const int wm = wid & 3;
    const int wn = wid >> 2;

    const __nv_bfloat16* gsrc[4] = {qhi, qlo, khi, klo};
#pragma unroll
    for (int tz = 0; tz < 4; tz++) {
        const __nv_bfloat16* g = gsrc[tz];
        const int rowbase = (tz < 2) ? t0 : s0;
        uint32_t sbase = smem_u32(&sm[tz][0]);
#pragma unroll
        for (int i = 0; i < 2; i++) {
            int idx = tid + i * 256;
            int r = idx >> 3;
            int seg = idx & 7;
            uint32_t sa = sbase + (uint32_t)(r * SC_STR * 2 + seg * 16);
            const __nv_bfloat16* gp = g + (size_t)(b * TT + rowbase + r) * DD +
                                      h * DH + seg * 8;
            CP16(sa, gp);
        }
    }
    CP_COMMIT(); CP_WAIT(0);
    __syncthreads();

    const uint32_t qh_b = smem_u32(&sm[0][0]);
    const uint32_t ql_b = smem_u32(&sm[1][0]);
    const uint32_t kh_b = smem_u32(&sm[2][0]);
    const uint32_t kl_b = smem_u32(&sm[3][0]);

    const int a_row = lane & 15;
    const int a_k8  = (lane >> 4) * 8;
    const int b_row = (lane & 7) + ((lane & 16) ? 8 : 0);
    const int b_k8  = (lane & 8) ? 8 : 0;

    float acc[4][4];
#pragma unroll
    for (int nt = 0; nt < 4; nt++)
#pragma unroll
        for (int i = 0; i < 4; i++) acc[nt][i] = 0.0f;

#pragma unroll
    for (int ks = 0; ks < 4; ks++) {
        uint32_t aH[4], aL[4];
        uint32_t ao = (uint32_t)((wm * 16 + a_row) * SC_STR * 2 + (ks * 16 + a_k8) * 2);
        ldsm4(aH, qh_b + ao);
        ldsm4(aL, ql_b + ao);
        uint32_t bH[2][4], bL[2][4];
#pragma unroll
        for (int p = 0; p < 2; p++) {
            uint32_t bo = (uint32_t)((wn * 32 + p * 16 + b_row) * SC_STR * 2 +
                                     (ks * 16 + b_k8) * 2);
            ldsm4(bH[p], kh_b + bo);
            ldsm4(bL[p], kl_b + bo);
        }
#pragma unroll
        for (int nt = 0; nt < 4; nt++) {
            const uint32_t* bhp = &bH[nt >> 1][(nt & 1) * 2];
            const uint32_t* blp = &bL[nt >> 1][(nt & 1) * 2];
            mma16816(acc[nt], aH, bhp);
            mma16816(acc[nt], aH, blp);
            mma16816(acc[nt], aL, bhp);
        }
    }

    __half* outp = scores + (size_t)bh * TS;
    const int row0 = t0 + wm * 16 + (lane >> 2);
#pragma unroll
    for (int nt = 0; nt < 4; nt++) {
        int col = s0 + wn * 32 + nt * 8 + (lane & 3) * 2;
#pragma unroll
        for (int half = 0; half < 2; half++) {
            int r = row0 + half * 8;
            __half2 hv;
            hv.x = __float2half_rn(acc[nt][half * 2 + 0] * 0.0625f);
            hv.y = __float2half_rn(acc[nt][half * 2 + 1] * 0.0625f);
            *(__half2*)(outp + r * TT + col) = hv;
        }
    }
}

// ---------------------------------------------------------------------------
// Kernel 5: expsum over bh -> inv (fp16 scores input).
// ---------------------------------------------------------------------------
__global__ __launch_bounds__(256) void expsum_kernel(const __half* __restrict__ scores,
                                                     float* __restrict__ inv) {
    __shared__ float red[256];
    const int ts0 = blockIdx.x * 64;
    const int t = ts0 >> 8;
    const int s_blk = ts0 & 255;
    if (s_blk + 63 <= t) return;

    const int lane_ts = threadIdx.x & 63;
    const int chunk = threadIdx.x >> 6;
    const int ts = ts0 + lane_ts;
    const int s = ts & 255;

    float sum = 0.0f;
    if (s > t) {
        const __half* p = scores + ts + (size_t)chunk * 256 * TS;
#pragma unroll 8
        for (int i = 0; i < 256; i++) sum += __expf(__half2float(p[(size_t)i * TS]));
    }
    red[threadIdx.x] = sum;
    __syncthreads();
    if (chunk == 0 && s > t) {
        float tot = red[lane_ts] + red[lane_ts + 64] +
                    red[lane_ts + 128] + red[lane_ts + 192];
        inv[ts] = 1.0f / tot;
    }
}

// ---------------------------------------------------------------------------
// Kernel 6: out = probs @ v_ on HMMA (fp16 scores input).
// ---------------------------------------------------------------------------
#define O_TILE (64 * SC_STR * 2)               // 9216 B
#define O_VH   0
#define O_VL   O_TILE
#define O_PH(tt) (2 * O_TILE + (tt) * O_TILE)
#define O_PL(tt) (6 * O_TILE + (tt) * O_TILE)
#define OUT_SMEM (10 * O_TILE)                 // 92160 B

__global__ __launch_bounds__(256) void out_hmma_kernel(
    const __half* __restrict__ scores,
    const float* __restrict__ inv,
    const float* __restrict__ v,
    float* __restrict__ out)
{
    extern __shared__ char smem[];
    const uint32_t sb = smem_u32(smem);
    const int bh = blockIdx.x;
    const int b = bh & (BB - 1);
    const int h = bh >> 6;

    const int tid = threadIdx.x;
    const int lane = tid & 31;
    const int wid = tid >> 5;
    const int wm = wid & 3;
    const int wn = wid >> 2;

    const __half* sbase = scores + (size_t)bh * TS;
    const float* vbase = v + (size_t)b * TT * DD + h * DH;

    const int a_row = lane & 15;
    const int a_k8  = (lane >> 4) * 8;
    const int bt_row = lane & 15;
    const int bt_n8  = (lane & 16) ? 8 : 0;

    float acc[4][4][4];
#pragma unroll
    for (int tt = 0; tt < 4; tt++)
#pragma unroll
        for (int nt = 0; nt < 4; nt++)
#pragma unroll
            for (int i = 0; i < 4; i++) acc[tt][nt][i] = 0.0f;

    for (int s0 = 0; s0 < TT; s0 += 64) {
        __nv_bfloat16* Vh = (__nv_bfloat16*)(smem + O_VH);
        __nv_bfloat16* Vl = (__nv_bfloat16*)(smem + O_VL);
#pragma unroll
        for (int i = 0; i < 4; i++) {
            int idx = tid + i * 256;
            int s = idx >> 4;
            int d4 = (idx & 15) * 4;
            float4 vv = *(const float4*)(vbase + (size_t)(s0 + s) * DD + d4);
            float vals[4] = {vv.x, vv.y, vv.z, vv.w};
            __nv_bfloat16 hi[4], lo[4];
#pragma unroll
            for (int j = 0; j < 4; j++) split_bf16(vals[j], hi[j], lo[j]);
            __nv_bfloat162 hp0; hp0.x = hi[0]; hp0.y = hi[1];
            __nv_bfloat162 hp1; hp1.x = hi[2]; hp1.y = hi[3];
            __nv_bfloat162 lp0; lp0.x = lo[0]; lp0.y = lo[1];
            __nv_bfloat162 lp1; lp1.x = lo[2]; lp1.y = lo[3];
            *(__nv_bfloat162*)(&Vh[s * SC_STR + d4])     = hp0;
            *(__nv_bfloat162*)(&Vh[s * SC_STR + d4 + 2]) = hp1;
            *(__nv_bfloat162*)(&Vl[s * SC_STR + d4])     = lp0;
            *(__nv_bfloat162*)(&Vl[s * SC_STR + d4 + 2]) = lp1;
        }

#pragma unroll
        for (int tt = 0; tt < 4; tt++) {
            const int t0 = tt * 64;
            const bool fm = (s0 + 64 <= t0);
            __nv_bfloat16* Ph = (__nv_bfloat16*)(smem + O_PH(tt));
            __nv_bfloat16* Pl = (__nv_bfloat16*)(smem + O_PL(tt));
            if (fm) {
                const __nv_bfloat16 uh = __float2bfloat16_rn(UNIF);
                __nv_bfloat162 up; up.x = uh; up.y = uh;
#pragma unroll
                for (int i = 0; i < 4; i++) {
                    int idx = tid + i * 256;
                    int r = idx >> 4;
                    int c4 = (idx & 15) * 4;
                    *(__nv_bfloat162*)(&Ph[r * SC_STR + c4])     = up;
                    *(__nv_bfloat162*)(&Ph[r * SC_STR + c4 + 2]) = up;
                }
            } else {
#pragma unroll
                for (int i = 0; i < 4; i++) {
                    int idx = tid + i * 256;
                    int r = idx >> 4;
                    int c4 = (idx & 15) * 4;
                    int t = t0 + r;
                    __half2 s01 = *(const __half2*)(sbase + t * TT + s0 + c4);
                    __half2 s23 = *(const __half2*)(sbase + t * TT + s0 + c4 + 2);
                    float4 iv = *(const float4*)(inv + t * TT + s0 + c4);
                    float scs[4] = {__half2float(s01.x), __half2float(s01.y),
                                    __half2float(s23.x), __half2float(s23.y)};
                    float ivs[4] = {iv.x, iv.y, iv.z, iv.w};
                    __nv_bfloat16 hi[4], lo[4];
#pragma unroll
                    for (int j = 0; j < 4; j++) {
                        int s = s0 + c4 + j;
                        float w = (s <= t) ? UNIF : __expf(scs[j]) * ivs[j];
                        split_bf16(w, hi[j], lo[j]);
                    }
                    __nv_bfloat162 hp0; hp0.x = hi[0]; hp0.y = hi[1];
                    __nv_bfloat162 hp1; hp1.x = hi[2]; hp1.y = hi[3];
                    __nv_bfloat162 lp0; lp0.x = lo[0]; lp0.y = lo[1];
                    __nv_bfloat162 lp1; lp1.x = lo[2]; lp1.y = lo[3];
                    *(__nv_bfloat162*)(&Ph[r * SC_STR + c4])     = hp0;
                    *(__nv_bfloat162*)(&Ph[r * SC_STR + c4 + 2]) = hp1;
                    *(__nv_bfloat162*)(&Pl[r * SC_STR + c4])     = lp0;
                    *(__nv_bfloat162*)(&Pl[r * SC_STR + c4 + 2]) = lp1;
                }
            }
        }
        __syncthreads();

#pragma unroll
        for (int ks = 0; ks < 4; ks++) {
            uint32_t bH[2][4], bL[2][4];
#pragma unroll
            for (int p = 0; p < 2; p++) {
                uint32_t bo = (uint32_t)((ks * 16 + bt_row) * SC_STR * 2 +
                                         (wn * 32 + p * 16 + bt_n8) * 2);
                ldsm4t(bH[p], sb + O_VH + bo);
                ldsm4t(bL[p], sb + O_VL + bo);
            }
            uint32_t ao = (uint32_t)((wm * 16 + a_row) * SC_STR * 2 +
                                     (ks * 16 + a_k8) * 2);
#pragma unroll
            for (int tt = 0; tt < 4; tt++) {
                const bool fm = (s0 + 64 <= tt * 64);
                uint32_t aH[4], aL[4];
                ldsm4(aH, sb + O_PH(tt) + ao);
                if (!fm) ldsm4(aL, sb + O_PL(tt) + ao);
#pragma unroll
                for (int nt = 0; nt < 4; nt++) {
                    const uint32_t* bhp = &bH[nt >> 1][(nt & 1) * 2];
                    const uint32_t* blp = &bL[nt >> 1][(nt & 1) * 2];
                    mma16816(acc[tt][nt], aH, bhp);
                    mma16816(acc[tt][nt], aH, blp);
                    if (!fm) mma16816(acc[tt][nt], aL, bhp);
                }
            }
        }
        __syncthreads();
    }

#pragma unroll
    for (int tt = 0; tt < 4; tt++) {
        const int row0 = tt * 64 + wm * 16 + (lane >> 2);
#pragma unroll
        for (int nt = 0; nt < 4; nt++) {
            int col = wn * 32 + nt * 8 + (lane & 3) * 2;
#pragma unroll
            for (int half = 0; half < 2; half++) {
                int r = row0 + half * 8;
                *(float2*)(out + (size_t)(b * TT + r) * DD + h * DH + col) =
                    make_float2(acc[tt][nt][half * 2 + 0], acc[tt][nt][half * 2 + 1]);
            }
        }
    }
}

// ---------------------------------------------------------------------------
// Launch
// ---------------------------------------------------------------------------
extern "C" void kernel_launch(void* const* d_in, const int* in_sizes, int n_in,
                              void* d_out, int out_size) {
    const float* x   = (const float*)d_in[0];
    const float* pos = (const float*)d_in[1];
    const float* W[3] = {(const float*)d_in[2], (const float*)d_in[3], (const float*)d_in[4]};
    float* out = (float*)d_out;

    __half *ah, *al, *wt, *scores;
    __nv_bfloat16 *qhi, *qlo, *khi, *klo;
    float *v, *inv;
    cudaGetSymbolAddress((void**)&ah, g_ah);
    cudaGetSymbolAddress((void**)&al, g_al);
    cudaGetSymbolAddress((void**)&wt, g_wt);
    cudaGetSymbolAddress((void**)&qhi, g_qhi);
    cudaGetSymbolAddress((void**)&qlo, g_qlo);
    cudaGetSymbolAddress((void**)&khi, g_khi);
    cudaGetSymbolAddress((void**)&klo, g_klo);
    cudaGetSymbolAddress((void**)&v, g_v);
    cudaGetSymbolAddress((void**)&scores, g_scores);
    cudaGetSymbolAddress((void**)&inv, g_inv);

    cudaFuncSetAttribute(gemm_hmma_kernel,
                         cudaFuncAttributeMaxDynamicSharedMemorySize, GEMM_SMEM);
    cudaFuncSetAttribute(out_hmma_kernel,
                         cudaFuncAttributeMaxDynamicSharedMemorySize, OUT_SMEM);

    // 1. (x + pos) -> fp16 hi/lo split
    {
        int n4 = BT * DD / 4;
        add_split_kernel<<<(n4 + 255) / 256, 256>>>(x, pos, ah, al);
    }

    // 2. weight transpose + fp16 convert (x3)
    {
        dim3 blk(32, 8);
        dim3 grid(DD / 32, DD / 32);
        for (int i = 0; i < 3; i++)
            wsplit_kernel<<<grid, blk>>>(W[i], wt + (size_t)i * DD * DD);
    }

    // 3. merged q/k/v projections (fp16 2-product, 3-stage pipeline)
    {
        dim3 grid(12, BT / G_BM);   // x = z*4 + ncol
        gemm_hmma_kernel<<<grid, 512, GEMM_SMEM>>>(
            ah, al, wt, qhi, qlo, khi, klo, v);
    }

    // 4. raw masked scores via HMMA (64x64 upper tiles; fp16 stores)
    {
        dim3 grid(TT / 64, TT / 64, HB);
        scores_hmma_kernel<<<grid, 256>>>(qhi, qlo, khi, klo, scores);
    }

    // 5. per-(t,s) exp-sum over bh -> inv (4-way bh-chunk parallel)
    expsum_kernel<<<TS / 64, 256>>>(scores, inv);

    // 6. output via HMMA: one CTA per bh, V tile reused across t-tiles
    out_hmma_kernel<<<HB, 256, OUT_SMEM>>>(scores, inv, v, out);
}

// round 17
// speedup vs baseline: 1.0623x; 1.0623x over previous
#include <cuda_runtime.h>
#include <cuda_bf16.h>
#include <cuda_fp16.h>
#include <math.h>
#include <stdint.h>

// Problem constants
#define BB   64
#define TT   256
#define DD   1024
#define HH   16
#define DH   64
#define BT   (BB*TT)      // 16384
#define HB   (HH*BB)      // 1024
#define TS   (TT*TT)      // 65536

#define UNIF (1.0f / 1024.0f)   // exactly representable in bf16

// ---------------------------------------------------------------------------
// Scratch (__device__ globals; no allocation allowed)
// ---------------------------------------------------------------------------
__device__ __half g_ah[BT * DD];                // 32 MB (fp16 hi of x+pos)
__device__ __half g_al[BT * DD];                // 32 MB (fp16 lo)
__device__ __half g_wt[3][DD * DD];             // 2 MB x3 (fp16, transposed [n][k])
__device__ __nv_bfloat16 g_qhi[BT * DD];        // 32 MB
__device__ __nv_bfloat16 g_qlo[BT * DD];        // 32 MB
__device__ __nv_bfloat16 g_khi[BT * DD];        // 32 MB
__device__ __nv_bfloat16 g_klo[BT * DD];        // 32 MB
__device__ float g_v[BT * DD];                  // 64 MB
__device__ float g_scores[(size_t)HB * TS];     // 256 MB (raw scores, s>t valid)
__device__ float g_inv[TS];                     // 256 KB

// ---------------------------------------------------------------------------
// helpers
// ---------------------------------------------------------------------------
__device__ __forceinline__ uint32_t smem_u32(const void* p) {
    uint32_t a;
    asm("{ .reg .u64 t; cvta.to.shared.u64 t, %1; cvt.u32.u64 %0, t; }" : "=r"(a) : "l"(p));
    return a;
}
__device__ __forceinline__ void ldsm4(uint32_t* r, uint32_t a) {
    asm volatile("ldmatrix.sync.aligned.m8n8.x4.shared.b16 {%0,%1,%2,%3}, [%4];"
                 : "=r"(r[0]), "=r"(r[1]), "=r"(r[2]), "=r"(r[3]) : "r"(a));
}
__device__ __forceinline__ void ldsm4t(uint32_t* r, uint32_t a) {
    asm volatile("ldmatrix.sync.aligned.m8n8.x4.trans.shared.b16 {%0,%1,%2,%3}, [%4];"
                 : "=r"(r[0]), "=r"(r[1]), "=r"(r[2]), "=r"(r[3]) : "r"(a));
}
__device__ __forceinline__ void mma16816(float* c, const uint32_t* a, const uint32_t* b) {
    asm volatile(
        "mma.sync.aligned.m16n8k16.row.col.f32.bf16.bf16.f32 "
        "{%0,%1,%2,%3}, {%4,%5,%6,%7}, {%8,%9}, {%0,%1,%2,%3};"
        : "+f"(c[0]), "+f"(c[1]), "+f"(c[2]), "+f"(c[3])
        : "r"(a[0]), "r"(a[1]), "r"(a[2]), "r"(a[3]), "r"(b[0]), "r"(b[1]));
}
__device__ __forceinline__ void mma16816h(float* c, const uint32_t* a, const uint32_t* b) {
    asm volatile(
        "mma.sync.aligned.m16n8k16.row.col.f32.f16.f16.f32 "
        "{%0,%1,%2,%3}, {%4,%5,%6,%7}, {%8,%9}, {%0,%1,%2,%3};"
        : "+f"(c[0]), "+f"(c[1]), "+f"(c[2]), "+f"(c[3])
        : "r"(a[0]), "r"(a[1]), "r"(a[2]), "r"(a[3]), "r"(b[0]), "r"(b[1]));
}
#define CP16(sa, gp) \
    asm volatile("cp.async.cg.shared.global [%0], [%1], 16;" :: "r"(sa), "l"(gp))
#define CP_COMMIT() asm volatile("cp.async.commit_group;" ::: "memory")
#define CP_WAIT(n)  asm volatile("cp.async.wait_group %0;" :: "n"(n) : "memory")

__device__ __forceinline__ void split_bf16(float a, __nv_bfloat16& h, __nv_bfloat16& l) {
    h = __float2bfloat16_rn(a);
    l = __float2bfloat16_rn(a - __bfloat162float(h));
}
__device__ __forceinline__ void split_fp16(float a, __half& h, __half& l) {
    h = __float2half_rn(a);
    l = __float2half_rn(a - __half2float(h));
}

// ---------------------------------------------------------------------------
// Kernel 1: (x + pos) -> split into fp16 hi/lo
// ---------------------------------------------------------------------------
__global__ void add_split_kernel(const float* __restrict__ x,
                                 const float* __restrict__ pos,
                                 __half* __restrict__ ah,
                                 __half* __restrict__ al) {
    int i4 = blockIdx.x * blockDim.x + threadIdx.x;
    int n4 = BT * DD / 4;
    if (i4 >= n4) return;
    int td4 = i4 % (TT * DD / 4);
    float4 xv = ((const float4*)x)[i4];
    float4 pv = ((const float4*)pos)[td4];
    float a[4] = {xv.x + pv.x, xv.y + pv.y, xv.z + pv.z, xv.w + pv.w};
    __half hi[4], lo[4];
#pragma unroll
    for (int j = 0; j < 4; j++) split_fp16(a[j], hi[j], lo[j]);
    __half2 h0; h0.x = hi[0]; h0.y = hi[1];
    __half2 h1; h1.x = hi[2]; h1.y = hi[3];
    __half2 l0; l0.x = lo[0]; l0.y = lo[1];
    __half2 l1; l1.x = lo[2]; l1.y = lo[3];
    ((__half2*)ah)[i4 * 2 + 0] = h0;
    ((__half2*)ah)[i4 * 2 + 1] = h1;
    ((__half2*)al)[i4 * 2 + 0] = l0;
    ((__half2*)al)[i4 * 2 + 1] = l1;
}

// ---------------------------------------------------------------------------
// Kernel 2: weight transpose + fp16 convert:  Wt[n][k] = fp16(W[k][n])
// ---------------------------------------------------------------------------
__global__ void wsplit_kernel(const float* __restrict__ W,
                              __half* __restrict__ wt) {
    __shared__ float tile[32][33];
    int k0 = blockIdx.x * 32;
    int n0 = blockIdx.y * 32;
    int tx = threadIdx.x;
    int ty = threadIdx.y;
#pragma unroll
    for (int i = 0; i < 32; i += 8)
        tile[ty + i][tx] = W[(size_t)(k0 + ty + i) * DD + n0 + tx];
    __syncthreads();
#pragma unroll
    for (int i = 0; i < 32; i += 8) {
        float v = tile[tx][ty + i];
        wt[(size_t)(n0 + ty + i) * DD + k0 + tx] = __float2half_rn(v);
    }
}

// ---------------------------------------------------------------------------
// Kernel 3: merged HMMA projection GEMM (fp16 2-product: aH*W + aL*W).
// 128x256 CTA tile, 32x64 warp tile, 4-stage cp.async pipeline.
// grid.x = z*4 + ncol (z: Wq/Wk/Wv).
// z<2: epilogue writes bf16 hi/lo split (q,k).  z==2: fp32 (v).
// ---------------------------------------------------------------------------
#define G_BM 128
#define G_BN 256
#define G_BK 32
#define G_NCH (DD / G_BK)        // 32
#define G_RS 40                   // smem row stride in halfs (80 B)
#define OFF_AH 0
#define OFF_AL (G_BM * G_RS * 2)                  // 10240
#define OFF_BH (2 * G_BM * G_RS * 2)              // 20480
#define G_STAGE (OFF_BH + G_BN * G_RS * 2)        // 40960
#define G_NSTAGE 4
#define GEMM_SMEM (G_NSTAGE * G_STAGE)            // 163840

__global__ __launch_bounds__(512) void gemm_hmma_kernel(
    const __half* __restrict__ Ah, const __half* __restrict__ Al,
    const __half* __restrict__ Wt,
    __nv_bfloat16* __restrict__ Qhi, __nv_bfloat16* __restrict__ Qlo,
    __nv_bfloat16* __restrict__ Khi, __nv_bfloat16* __restrict__ Klo,
    float* __restrict__ V)
{
    extern __shared__ char smem[];
    const uint32_t sb = smem_u32(smem);
    const int tid = threadIdx.x;
    const int lane = tid & 31;
    const int wid = tid >> 5;
    const int wm = wid & 3;
    const int wn = wid >> 2;
    const int z = blockIdx.x >> 2;
    const int brow = blockIdx.y * G_BM;
    const int bcol = (blockIdx.x & 3) * G_BN;

    const __half* Bh = Wt + (size_t)z * DD * DD;

    const int acrow = tid >> 2;
    const int acseg = tid & 3;
    const uint32_t a_soff = (uint32_t)(acrow * (G_RS * 2) + acseg * 16);
    const size_t ga_base = (size_t)(brow + acrow) * DD + acseg * 8;

    float acc[2][8][4];
#pragma unroll
    for (int mt = 0; mt < 2; mt++)
#pragma unroll
        for (int nt = 0; nt < 8; nt++)
#pragma unroll
            for (int i = 0; i < 4; i++) acc[mt][nt][i] = 0.0f;

    auto load_stage = [&](int ch, int stg) {
        uint32_t st = sb + stg * G_STAGE;
        size_t goff = (size_t)ch * G_BK;
        CP16(st + OFF_AH + a_soff, Ah + ga_base + goff);
        CP16(st + OFF_AL + a_soff, Al + ga_base + goff);
#pragma unroll
        for (int i = 0; i < 2; i++) {
            int idx = tid + i * 512;
            int r = idx >> 2;
            int seg = idx & 3;
            uint32_t so = (uint32_t)(r * (G_RS * 2) + seg * 16);
            size_t gb = (size_t)(bcol + r) * DD + seg * 8 + goff;
            CP16(st + OFF_BH + so, Bh + gb);
        }
        CP_COMMIT();
    };

    load_stage(0, 0);
    load_stage(1, 1);
    load_stage(2, 2);

    const int a_row = lane & 15;
    const int a_k8  = (lane >> 4) * 8;
    const int b_row = (lane & 7) + ((lane & 16) ? 8 : 0);
    const int b_k8  = (lane & 8) ? 8 : 0;

    for (int ch = 0; ch < G_NCH; ch++) {
        if (ch + 3 < G_NCH) {
            load_stage(ch + 3, (ch + 3) % G_NSTAGE);
            CP_WAIT(3);
        } else if (ch + 2 < G_NCH) {
            CP_WAIT(2);
        } else if (ch + 1 < G_NCH) {
            CP_WAIT(1);
        } else {
            CP_WAIT(0);
        }
        __syncthreads();

        const uint32_t st = sb + (ch % G_NSTAGE) * G_STAGE;
#pragma unroll
        for (int ks = 0; ks < 2; ks++) {
            uint32_t aH[2][4], aL[2][4];
#pragma unroll
            for (int mt = 0; mt < 2; mt++) {
                uint32_t ao = st + OFF_AH +
                    (uint32_t)((wm * 32 + mt * 16 + a_row) * (G_RS * 2) +
                               (ks * 16 + a_k8) * 2);
                ldsm4(aH[mt], ao);
                ldsm4(aL[mt], ao + (OFF_AL - OFF_AH));
            }
#pragma unroll
            for (int ph = 0; ph < 2; ph++) {
                uint32_t bH[2][4];
#pragma unroll
                for (int p = 0; p < 2; p++) {
                    uint32_t bo = st + OFF_BH +
                        (uint32_t)((wn * 64 + (ph * 2 + p) * 16 + b_row) * (G_RS * 2) +
                                   (ks * 16 + b_k8) * 2);
                    ldsm4(bH[p], bo);
                }
#pragma unroll
                for (int mt = 0; mt < 2; mt++)
#pragma unroll
                    for (int nl = 0; nl < 4; nl++) {
                        const uint32_t* bhp = &bH[nl >> 1][(nl & 1) * 2];
                        float* a = acc[mt][ph * 4 + nl];
                        mma16816h(a, aH[mt], bhp);
                        mma16816h(a, aL[mt], bhp);
                    }
            }
        }
        __syncthreads();
    }

    __nv_bfloat16* Ohi = (z == 0) ? Qhi : Khi;
    __nv_bfloat16* Olo = (z == 0) ? Qlo : Klo;
#pragma unroll
    for (int mt = 0; mt < 2; mt++) {
        int row = brow + wm * 32 + mt * 16 + (lane >> 2);
#pragma unroll
        for (int nt = 0; nt < 8; nt++) {
            int col = bcol + wn * 64 + nt * 8 + (lane & 3) * 2;
            if (z == 2) {
                *(float2*)(V + (size_t)row * DD + col) =
                    make_float2(acc[mt][nt][0], acc[mt][nt][1]);
                *(float2*)(V + (size_t)(row + 8) * DD + col) =
                    make_float2(acc[mt][nt][2], acc[mt][nt][3]);
            } else {
#pragma unroll
                for (int half = 0; half < 2; half++) {
                    int r = row + half * 8;
                    __nv_bfloat16 h0, l0, h1, l1;
                    split_bf16(acc[mt][nt][half * 2 + 0], h0, l0);
                    split_bf16(acc[mt][nt][half * 2 + 1], h1, l1);
                    __nv_bfloat162 hp; hp.x = h0; hp.y = h1;
                    __nv_bfloat162 lp; lp.x = l0; lp.y = l1;
                    *(__nv_bfloat162*)(Ohi + (size_t)r * DD + col) = hp;
                    *(__nv_bfloat162*)(Olo + (size_t)r * DD + col) = lp;
                }
            }
        }
    }
}

// ---------------------------------------------------------------------------
// Kernel 4: HMMA scores, 64x64 upper tiles (bf16 3-product, proven).
// fp32 stores (wide-access rule: never narrow the store path).
// ---------------------------------------------------------------------------
#define SC_STR 72   // smem row stride in halfs (144B)

__global__ __launch_bounds__(256) void scores_hmma_kernel(
    const __nv_bfloat16* __restrict__ qhi, const __nv_bfloat16* __restrict__ qlo,
    const __nv_bfloat16* __restrict__ khi, const __nv_bfloat16* __restrict__ klo,
    float* __restrict__ scores)
{
    const int t0 = blockIdx.y * 64;
    const int s0 = blockIdx.x * 64;
    if (s0 < t0) return;   // fully masked tile
    const int bh = blockIdx.z;
    const int b = bh & (BB - 1);
    const int h = bh >> 6;

    __shared__ __nv_bfloat16 sm[4][64 * SC_STR];

    const int tid = threadIdx.x;
    const int lane = tid & 31;
    const int wid = tid >> 5;
    const int wm = wid & 3;
    const int wn = wid >> 2;

    const __nv_bfloat16* gsrc[4] = {qhi, qlo, khi, klo};
#pragma unroll
    for (int tz = 0; tz < 4; tz++) {
        const __nv_bfloat16* g = gsrc[tz];
        const int rowbase = (tz < 2) ? t0 : s0;
        uint32_t sbase = smem_u32(&sm[tz][0]);
#pragma unroll
        for (int i = 0; i < 2; i++) {
            int idx = tid + i * 256;
            int r = idx >> 3;
            int seg = idx & 7;
            uint32_t sa = sbase + (uint32_t)(r * SC_STR * 2 + seg * 16);
            const __nv_bfloat16* gp = g + (size_t)(b * TT + rowbase + r) * DD +
                                      h * DH + seg * 8;
            CP16(sa, gp);
        }
    }
    CP_COMMIT(); CP_WAIT(0);
    __syncthreads();

    const uint32_t qh_b = smem_u32(&sm[0][0]);
    const uint32_t ql_b = smem_u32(&sm[1][0]);
    const uint32_t kh_b = smem_u32(&sm[2][0]);
    const uint32_t kl_b = smem_u32(&sm[3][0]);

    const int a_row = lane & 15;
    const int a_k8  = (lane >> 4) * 8;
    const int b_row = (lane & 7) + ((lane & 16) ? 8 : 0);
    const int b_k8  = (lane & 8) ? 8 : 0;

    float acc[4][4];
#pragma unroll
    for (int nt = 0; nt < 4; nt++)
#pragma unroll
        for (int i = 0; i < 4; i++) acc[nt][i] = 0.0f;

#pragma unroll
    for (int ks = 0; ks < 4; ks++) {
        uint32_t aH[4], aL[4];
        uint32_t ao = (uint32_t)((wm * 16 + a_row) * SC_STR * 2 + (ks * 16 + a_k8) * 2);
        ldsm4(aH, qh_b + ao);
        ldsm4(aL, ql_b + ao);
        uint32_t bH[2][4], bL[2][4];
#pragma unroll
        for (int p = 0; p < 2; p++) {
            uint32_t bo = (uint32_t)((wn * 32 + p * 16 + b_row) * SC_STR * 2 +
                                     (ks * 16 + b_k8) * 2);
            ldsm4(bH[p], kh_b + bo);
            ldsm4(bL[p], kl_b + bo);
        }
#pragma unroll
        for (int nt = 0; nt < 4; nt++) {
            const uint32_t* bhp = &bH[nt >> 1][(nt & 1) * 2];
            const uint32_t* blp = &bL[nt >> 1][(nt & 1) * 2];
            mma16816(acc[nt], aH, bhp);
            mma16816(acc[nt], aH, blp);
            mma16816(acc[nt], aL, bhp);
        }
    }

    float* outp = scores + (size_t)bh * TS;
    const int row0 = t0 + wm * 16 + (lane >> 2);
#pragma unroll
    for (int nt = 0; nt < 4; nt++) {
        int col = s0 + wn * 32 + nt * 8 + (lane & 3) * 2;
#pragma unroll
        for (int half = 0; half < 2; half++) {
            int r = row0 + half * 8;
            *(float2*)(outp + r * TT + col) =
                make_float2(acc[nt][half * 2 + 0] * 0.0625f,
                            acc[nt][half * 2 + 1] * 0.0625f);
        }
    }
}

// ---------------------------------------------------------------------------
// Kernel 5: expsum over bh -> inv.  4-way bh-chunk parallelism per column.
// ---------------------------------------------------------------------------
__global__ __launch_bounds__(256) void expsum_kernel(const float* __restrict__ scores,
                                                     float* __restrict__ inv) {
    __shared__ float red[256];
    const int ts0 = blockIdx.x * 64;
    const int t = ts0 >> 8;
    const int s_blk = ts0 & 255;
    if (s_blk + 63 <= t) return;

    const int lane_ts = threadIdx.x & 63;
    const int chunk = threadIdx.x >> 6;
    const int ts = ts0 + lane_ts;
    const int s = ts & 255;

    float sum = 0.0f;
    if (s > t) {
        const float* p = scores + ts + (size_t)chunk * 256 * TS;
#pragma unroll 8
        for (int i = 0; i < 256; i++) sum += __expf(p[(size_t)i * TS]);
    }
    red[threadIdx.x] = sum;
    __syncthreads();
    if (chunk == 0 && s > t) {
        float tot = red[lane_ts] + red[lane_ts + 64] +
                    red[lane_ts + 128] + red[lane_ts + 192];
        inv[ts] = 1.0f / tot;
    }
}

// ---------------------------------------------------------------------------
// Kernel 6: out = probs @ v_ on HMMA.  ONE CTA PER bh (proven 946 version).
// ---------------------------------------------------------------------------
#define O_TILE (64 * SC_STR * 2)               // 9216 B
#define O_VH   0
#define O_VL   O_TILE
#define O_PH(tt) (2 * O_TILE + (tt) * O_TILE)
#define O_PL(tt) (6 * O_TILE + (tt) * O_TILE)
#define OUT_SMEM (10 * O_TILE)                 // 92160 B

__global__ __launch_bounds__(256) void out_hmma_kernel(
    const float* __restrict__ scores,
    const float* __restrict__ inv,
    const float* __restrict__ v,
    float* __restrict__ out)
{
    extern __shared__ char smem[];
    const uint32_t sb = smem_u32(smem);
    const int bh = blockIdx.x;
    const int b = bh & (BB - 1);
    const int h = bh >> 6;

    const int tid = threadIdx.x;
    const int lane = tid & 31;
    const int wid = tid >> 5;
    const int wm = wid & 3;
    const int wn = wid >> 2;

    const float* sbase = scores + (size_t)bh * TS;
    const float* vbase = v + (size_t)b * TT * DD + h * DH;

    const int a_row = lane & 15;
    const int a_k8  = (lane >> 4) * 8;
    const int bt_row = lane & 15;
    const int bt_n8  = (lane & 16) ? 8 : 0;

    float acc[4][4][4];
#pragma unroll
    for (int tt = 0; tt < 4; tt++)
#pragma unroll
        for (int nt = 0; nt < 4; nt++)
#pragma unroll
            for (int i = 0; i < 4; i++) acc[tt][nt][i] = 0.0f;

    for (int s0 = 0; s0 < TT; s0 += 64) {
        __nv_bfloat16* Vh = (__nv_bfloat16*)(smem + O_VH);
        __nv_bfloat16* Vl = (__nv_bfloat16*)(smem + O_VL);
#pragma unroll
        for (int i = 0; i < 4; i++) {
            int idx = tid + i * 256;
            int s = idx >> 4;
            int d4 = (idx & 15) * 4;
            float4 vv = *(const float4*)(vbase + (size_t)(s0 + s) * DD + d4);
            float vals[4] = {vv.x, vv.y, vv.z, vv.w};
            __nv_bfloat16 hi[4], lo[4];
#pragma unroll
            for (int j = 0; j < 4; j++) split_bf16(vals[j], hi[j], lo[j]);
            __nv_bfloat162 hp0; hp0.x = hi[0]; hp0.y = hi[1];
            __nv_bfloat162 hp1; hp1.x = hi[2]; hp1.y = hi[3];
            __nv_bfloat162 lp0; lp0.x = lo[0]; lp0.y = lo[1];
            __nv_bfloat162 lp1; lp1.x = lo[2]; lp1.y = lo[3];
            *(__nv_bfloat162*)(&Vh[s * SC_STR + d4])     = hp0;
            *(__nv_bfloat162*)(&Vh[s * SC_STR + d4 + 2]) = hp1;
            *(__nv_bfloat162*)(&Vl[s * SC_STR + d4])     = lp0;
            *(__nv_bfloat162*)(&Vl[s * SC_STR + d4 + 2]) = lp1;
        }

#pragma unroll
        for (int tt = 0; tt < 4; tt++) {
            const int t0 = tt * 64;
            const bool fm = (s0 + 64 <= t0);
            __nv_bfloat16* Ph = (__nv_bfloat16*)(smem + O_PH(tt));
            __nv_bfloat16* Pl = (__nv_bfloat16*)(smem + O_PL(tt));
            if (fm) {
                const __nv_bfloat16 uh = __float2bfloat16_rn(UNIF);
                __nv_bfloat162 up; up.x = uh; up.y = uh;
#pragma unroll
                for (int i = 0; i < 4; i++) {
                    int idx = tid + i * 256;
                    int r = idx >> 4;
                    int c4 = (idx & 15) * 4;
                    *(__nv_bfloat162*)(&Ph[r * SC_STR + c4])     = up;
                    *(__nv_bfloat162*)(&Ph[r * SC_STR + c4 + 2]) = up;
                }
            } else {
#pragma unroll
                for (int i = 0; i < 4; i++) {
                    int idx = tid + i * 256;
                    int r = idx >> 4;
                    int c4 = (idx & 15) * 4;
                    int t = t0 + r;
                    float4 sc = *(const float4*)(sbase + t * TT + s0 + c4);
                    float4 iv = *(const float4*)(inv + t * TT + s0 + c4);
                    float scs[4] = {sc.x, sc.y, sc.z, sc.w};
                    float ivs[4] = {iv.x, iv.y, iv.z, iv.w};
                    __nv_bfloat16 hi[4], lo[4];
#pragma unroll
                    for (int j = 0; j < 4; j++) {
                        int s = s0 + c4 + j;
                        float w = (s <= t) ? UNIF : __expf(scs[j]) * ivs[j];
                        split_bf16(w, hi[j], lo[j]);
                    }
                    __nv_bfloat162 hp0; hp0.x = hi[0]; hp0.y = hi[1];
                    __nv_bfloat162 hp1; hp1.x = hi[2]; hp1.y = hi[3];
                    __nv_bfloat162 lp0; lp0.x = lo[0]; lp0.y = lo[1];
                    __nv_bfloat162 lp1; lp1.x = lo[2]; lp1.y = lo[3];
                    *(__nv_bfloat162*)(&Ph[r * SC_STR + c4])     = hp0;
                    *(__nv_bfloat162*)(&Ph[r * SC_STR + c4 + 2]) = hp1;
                    *(__nv_bfloat162*)(&Pl[r * SC_STR + c4])     = lp0;
                    *(__nv_bfloat162*)(&Pl[r * SC_STR + c4 + 2]) = lp1;
                }
            }
        }
        __syncthreads();

#pragma unroll
        for (int ks = 0; ks < 4; ks++) {
            uint32_t bH[2][4], bL[2][4];
#pragma unroll
            for (int p = 0; p < 2; p++) {
                uint32_t bo = (uint32_t)((ks * 16 + bt_row) * SC_STR * 2 +
                                         (wn * 32 + p * 16 + bt_n8) * 2);
                ldsm4t(bH[p], sb + O_VH + bo);
                ldsm4t(bL[p], sb + O_VL + bo);
            }
            uint32_t ao = (uint32_t)((wm * 16 + a_row) * SC_STR * 2 +
                                     (ks * 16 + a_k8) * 2);
#pragma unroll
            for (int tt = 0; tt < 4; tt++) {
                const bool fm = (s0 + 64 <= tt * 64);
                uint32_t aH[4], aL[4];
                ldsm4(aH, sb + O_PH(tt) + ao);
                if (!fm) ldsm4(aL, sb + O_PL(tt) + ao);
#pragma unroll
                for (int nt = 0; nt < 4; nt++) {
                    const uint32_t* bhp = &bH[nt >> 1][(nt & 1) * 2];
                    const uint32_t* blp = &bL[nt >> 1][(nt & 1) * 2];
                    mma16816(acc[tt][nt], aH, bhp);
                    mma16816(acc[tt][nt], aH, blp);
                    if (!fm) mma16816(acc[tt][nt], aL, bhp);
                }
            }
        }
        __syncthreads();
    }

#pragma unroll
    for (int tt = 0; tt < 4; tt++) {
        const int row0 = tt * 64 + wm * 16 + (lane >> 2);
#pragma unroll
        for (int nt = 0; nt < 4; nt++) {
            int col = wn * 32 + nt * 8 + (lane & 3) * 2;
#pragma unroll
            for (int half = 0; half < 2; half++) {
                int r = row0 + half * 8;
                *(float2*)(out + (size_t)(b * TT + r) * DD + h * DH + col) =
                    make_float2(acc[tt][nt][half * 2 + 0], acc[tt][nt][half * 2 + 1]);
            }
        }
    }
}

// ---------------------------------------------------------------------------
// Launch
// ---------------------------------------------------------------------------
extern "C" void kernel_launch(void* const* d_in, const int* in_sizes, int n_in,
                              void* d_out, int out_size) {
    const float* x   = (const float*)d_in[0];
    const float* pos = (const float*)d_in[1];
    const float* W[3] = {(const float*)d_in[2], (const float*)d_in[3], (const float*)d_in[4]};
    float* out = (float*)d_out;

    __half *ah, *al, *wt;
    __nv_bfloat16 *qhi, *qlo, *khi, *klo;
    float *v, *scores, *inv;
    cudaGetSymbolAddress((void**)&ah, g_ah);
    cudaGetSymbolAddress((void**)&al, g_al);
    cudaGetSymbolAddress((void**)&wt, g_wt);
    cudaGetSymbolAddress((void**)&qhi, g_qhi);
    cudaGetSymbolAddress((void**)&qlo, g_qlo);
    cudaGetSymbolAddress((void**)&khi, g_khi);
    cudaGetSymbolAddress((void**)&klo, g_klo);
    cudaGetSymbolAddress((void**)&v, g_v);
    cudaGetSymbolAddress((void**)&scores, g_scores);
    cudaGetSymbolAddress((void**)&inv, g_inv);

    cudaFuncSetAttribute(gemm_hmma_kernel,
                         cudaFuncAttributeMaxDynamicSharedMemorySize, GEMM_SMEM);
    cudaFuncSetAttribute(out_hmma_kernel,
                         cudaFuncAttributeMaxDynamicSharedMemorySize, OUT_SMEM);

    // 1. (x + pos) -> fp16 hi/lo split
    {
        int n4 = BT * DD / 4;
        add_split_kernel<<<(n4 + 255) / 256, 256>>>(x, pos, ah, al);
    }

    // 2. weight transpose + fp16 convert (x3)
    {
        dim3 blk(32, 8);
        dim3 grid(DD / 32, DD / 32);
        for (int i = 0; i < 3; i++)
            wsplit_kernel<<<grid, blk>>>(W[i], wt + (size_t)i * DD * DD);
    }

    // 3. merged q/k/v projections (fp16 2-product, 4-stage pipeline)
    {
        dim3 grid(12, BT / G_BM);   // x = z*4 + ncol
        gemm_hmma_kernel<<<grid, 512, GEMM_SMEM>>>(
            ah, al, wt, qhi, qlo, khi, klo, v);
    }

    // 4. raw masked scores via HMMA (64x64 upper tiles; fp32 stores)
    {
        dim3 grid(TT / 64, TT / 64, HB);
        scores_hmma_kernel<<<grid, 256>>>(qhi, qlo, khi, klo, scores);
    }

    // 5. per-(t,s) exp-sum over bh -> inv (4-way bh-chunk parallel)
    expsum_kernel<<<TS / 64, 256>>>(scores, inv);

    // 6. output via HMMA: one CTA per bh, V tile reused across t-tiles
    out_hmma_kernel<<<HB, 256, OUT_SMEM>>>(scores, inv, v, out);
}